// round 5
// baseline (speedup 1.0000x reference)
#include <cuda_runtime.h>
#include <cuda_bf16.h>
#include <math.h>

// ---------------------------------------------------------------------------
// CandiRec: query MLP -> cosine sims vs 500k items -> top-20 -> fixed_idx + loss
// Shapes: B=64, LQ=4096, LD=512, D=128, N=500000 (N read at runtime)
// ---------------------------------------------------------------------------

#define B_SZ   64
#define LQ     4096
#define LD     512
#define DIM    128
#define MAXN   500000
#define TOPK   20
#define TSPLIT 8
#define NEG_HUGE (-3.402823466e38f)

// ------------------------- device scratch (no allocs allowed) ---------------
__device__ float g_hpart[16 * B_SZ * LD];        // split-K partials of q@W1
__device__ float g_h[B_SZ * LD];                 // h = q@W1 + b1
__device__ float g_qn[B_SZ * DIM];               // l2-normalized query
__device__ float g_sims[(size_t)B_SZ * MAXN];    // 128 MB sims scratch
__device__ float g_pv[B_SZ * TSPLIT * TOPK];     // per-split partial topk vals
__device__ int   g_pi[B_SZ * TSPLIT * TOPK];     // per-split partial topk idx
__device__ int   g_topidx[B_SZ * TOPK];
__device__ float g_rowloss[B_SZ];
__device__ int   g_is64_flag;                    // target dtype: 1 = int64

// ------------------------- helpers -----------------------------------------
__device__ __forceinline__ unsigned long long pack2(float x, float y) {
    unsigned long long r;
    asm("mov.b64 %0, {%1, %2};" : "=l"(r) : "f"(x), "f"(y));
    return r;
}
__device__ __forceinline__ float2 unpack2(unsigned long long v) {
    float2 r;
    asm("mov.b64 {%0, %1}, %2;" : "=f"(r.x), "=f"(r.y) : "l"(v));
    return r;
}
#define FMA2(acc, a, b) \
    asm("fma.rn.f32x2 %0, %1, %2, %3;" : "=l"(acc) : "l"(a), "l"(b), "l"(acc))

__device__ __forceinline__ bool better(float v, int i, float v2, int i2) {
    // true if (v,i) ranks strictly above (v2,i2): higher value, ties -> lower idx
    return (v > v2) || (v == v2 && i < i2);
}

// ------------------------- K1a: h partials = q @ W1 (split-K) ---------------
// grid (8 col-chunks of 64, 16 k-splits of 256), 256 threads
// inner product via packed fma.rn.f32x2 (2 FMAs per issued instruction)
__global__ void __launch_bounds__(256) gemm1_partial(const float* __restrict__ q,
                                                     const float* __restrict__ W1) {
    __shared__ float shq[32][68];
    __shared__ float shw[32][68];
    const int cb = blockIdx.x * 64;
    const int k0 = blockIdx.y * 256;
    const int tid = threadIdx.x;
    const int r0 = (tid >> 4) * 4;
    const int c0 = (tid & 15) * 4;
    unsigned long long acc2[4][2];   // 4 rows x (2 packed col-pairs) = 4x4 fp32
#pragma unroll
    for (int r = 0; r < 4; r++) { acc2[r][0] = 0ull; acc2[r][1] = 0ull; }

    for (int kc = 0; kc < 256; kc += 32) {
        // load q chunk [64 rows][32 k] -> shq[k][row]
#pragma unroll
        for (int u = 0; u < 2; u++) {
            int f = u * 256 + tid;                 // 0..511
            int row = f >> 3;
            int jj = (f & 7) * 4;
            float4 v = *(const float4*)&q[(size_t)row * LQ + k0 + kc + jj];
            shq[jj + 0][row] = v.x; shq[jj + 1][row] = v.y;
            shq[jj + 2][row] = v.z; shq[jj + 3][row] = v.w;
        }
        // load W1 chunk [32 k][64 c] -> shw[k][c]
#pragma unroll
        for (int u = 0; u < 2; u++) {
            int f = u * 256 + tid;
            int kk = f >> 4;
            int cc = (f & 15) * 4;
            float4 v = *(const float4*)&W1[(size_t)(k0 + kc + kk) * LD + cb + cc];
            *(float4*)&shw[kk][cc] = v;
        }
        __syncthreads();
#pragma unroll 8
        for (int k = 0; k < 32; k++) {
            float4 qv = *(const float4*)&shq[k][r0];
            float4 wv = *(const float4*)&shw[k][c0];
            unsigned long long w01 = pack2(wv.x, wv.y);
            unsigned long long w23 = pack2(wv.z, wv.w);
            float qarr[4] = {qv.x, qv.y, qv.z, qv.w};
#pragma unroll
            for (int r = 0; r < 4; r++) {
                unsigned long long qq = pack2(qarr[r], qarr[r]);
                FMA2(acc2[r][0], w01, qq);
                FMA2(acc2[r][1], w23, qq);
            }
        }
        __syncthreads();
    }
#pragma unroll
    for (int r = 0; r < 4; r++) {
        float2 a01 = unpack2(acc2[r][0]);
        float2 a23 = unpack2(acc2[r][1]);
        float* dst = &g_hpart[((size_t)blockIdx.y * B_SZ + r0 + r) * LD + cb + c0];
        dst[0] = a01.x; dst[1] = a01.y; dst[2] = a23.x; dst[3] = a23.y;
    }
}

// ------------------------- K1a': reduce split-K + bias ----------------------
__global__ void gemm1_reduce(const float* __restrict__ b1) {
    int o = blockIdx.x * 256 + threadIdx.x;   // 0..32767
    int c = o & (LD - 1);
    float s = b1[c];
#pragma unroll
    for (int y = 0; y < 16; y++) s += g_hpart[(size_t)y * (B_SZ * LD) + o];
    g_h[o] = s;
}

// ------------------------- K1b: query = h@W2 + b2, l2-normalize -------------
// 64 blocks (row each), 128 threads (col each)
__global__ void gemm2_norm(const float* __restrict__ W2, const float* __restrict__ b2) {
    __shared__ float hrow[LD];
    __shared__ float red[4];
    const int b = blockIdx.x, t = threadIdx.x;
    *(float4*)&hrow[t * 4] = *(const float4*)&g_h[(size_t)b * LD + t * 4];
    __syncthreads();
    float s = b2[t];
#pragma unroll 8
    for (int k = 0; k < LD; k++) s += hrow[k] * W2[(size_t)k * DIM + t];
    float sq = s * s;
#pragma unroll
    for (int o = 16; o; o >>= 1) sq += __shfl_xor_sync(0xffffffffu, sq, o);
    if ((t & 31) == 0) red[t >> 5] = sq;
    __syncthreads();
    float tot = red[0] + red[1] + red[2] + red[3];
    g_qn[(size_t)b * DIM + t] = s * rsqrtf(tot + 1e-12f);
}

// ------------------------- K2: sims = qn @ l2n(emb).T ----------------------
// block: 256 threads, tile 64 rows x 128 items; thread tile 4 rows x 8 items
// fp32 via packed fma.rn.f32x2
__global__ void __launch_bounds__(256, 1) sims_kernel(const float* __restrict__ emb, int N) {
    __shared__ float sh_q[32][68];     // [k][row]
    __shared__ float sh_e[32][136];    // [k][item]
    __shared__ float sh_inv[128];
    const int i0 = blockIdx.x * 128;
    const int tid = threadIdx.x;
    const int r0 = (tid >> 4) * 4;     // 16 row groups
    const int c0 = (tid & 15) * 8;     // 16 item groups

    unsigned long long acc[4][4];
#pragma unroll
    for (int r = 0; r < 4; r++)
#pragma unroll
        for (int p = 0; p < 4; p++) acc[r][p] = 0ull;

    float ss = 0.f;   // per-item sum of squares (threads 0..127 own item tid)

    for (int kc = 0; kc < DIM; kc += 32) {
        // load emb chunk: 128 items x 32 k = 1024 float4s
#pragma unroll
        for (int u = 0; u < 4; u++) {
            int f = u * 256 + tid;             // 0..1023
            int item = f >> 3;
            int jj = (f & 7) * 4;
            int gi = i0 + item;
            float4 v = make_float4(0.f, 0.f, 0.f, 0.f);
            if (gi < N) v = *(const float4*)&emb[(size_t)gi * DIM + kc + jj];
            sh_e[jj + 0][item] = v.x; sh_e[jj + 1][item] = v.y;
            sh_e[jj + 2][item] = v.z; sh_e[jj + 3][item] = v.w;
        }
        // load qn chunk: 64 rows x 32 k = 512 float4s
#pragma unroll
        for (int u = 0; u < 2; u++) {
            int f = u * 256 + tid;
            int row = f >> 3;
            int jj = (f & 7) * 4;
            float4 v = *(const float4*)&g_qn[(size_t)row * DIM + kc + jj];
            sh_q[jj + 0][row] = v.x; sh_q[jj + 1][row] = v.y;
            sh_q[jj + 2][row] = v.z; sh_q[jj + 3][row] = v.w;
        }
        __syncthreads();

        if (tid < 128) {
#pragma unroll 8
            for (int k = 0; k < 32; k++) { float e = sh_e[k][tid]; ss += e * e; }
        }

#pragma unroll 8
        for (int k = 0; k < 32; k++) {
            float4 qv = *(const float4*)&sh_q[k][r0];
            float4 e0 = *(const float4*)&sh_e[k][c0];
            float4 e1 = *(const float4*)&sh_e[k][c0 + 4];
            unsigned long long ea = pack2(e0.x, e0.y);
            unsigned long long eb = pack2(e0.z, e0.w);
            unsigned long long ec = pack2(e1.x, e1.y);
            unsigned long long ed = pack2(e1.z, e1.w);
            float qarr[4] = {qv.x, qv.y, qv.z, qv.w};
#pragma unroll
            for (int r = 0; r < 4; r++) {
                unsigned long long qq = pack2(qarr[r], qarr[r]);
                FMA2(acc[r][0], ea, qq);
                FMA2(acc[r][1], eb, qq);
                FMA2(acc[r][2], ec, qq);
                FMA2(acc[r][3], ed, qq);
            }
        }
        __syncthreads();
    }

    if (tid < 128) sh_inv[tid] = rsqrtf(ss + 1e-12f);
    __syncthreads();

    const bool full = (i0 + 128 <= N) && ((N & 3) == 0);
#pragma unroll
    for (int r = 0; r < 4; r++) {
        size_t base = (size_t)(r0 + r) * N + i0 + c0;
        float2 a0 = unpack2(acc[r][0]);
        float2 a1 = unpack2(acc[r][1]);
        float2 a2 = unpack2(acc[r][2]);
        float2 a3 = unpack2(acc[r][3]);
        float o0 = a0.x * sh_inv[c0 + 0], o1 = a0.y * sh_inv[c0 + 1];
        float o2 = a1.x * sh_inv[c0 + 2], o3 = a1.y * sh_inv[c0 + 3];
        float o4 = a2.x * sh_inv[c0 + 4], o5 = a2.y * sh_inv[c0 + 5];
        float o6 = a3.x * sh_inv[c0 + 6], o7 = a3.y * sh_inv[c0 + 7];
        if (full) {
            float4 v0 = make_float4(o0, o1, o2, o3);
            float4 v1 = make_float4(o4, o5, o6, o7);
            *(float4*)&g_sims[base] = v0;
            *(float4*)&g_sims[base + 4] = v1;
        } else {
            float ov[8] = {o0, o1, o2, o3, o4, o5, o6, o7};
#pragma unroll
            for (int p = 0; p < 8; p++)
                if (i0 + c0 + p < N) g_sims[base + p] = ov[p];
        }
    }
}

// ------------------------- K3a: per-(row,split) partial top-20 --------------
// grid (64 rows, TSPLIT splits), 256 threads. float4 vectorized streaming.
__global__ void __launch_bounds__(256) topk_part(int N) {
    const int b = blockIdx.x;
    const int s = blockIdx.y;
    int chunk = ((N + TSPLIT - 1) / TSPLIT + 3) & ~3;   // 4-aligned chunk
    const int lo = s * chunk;
    const int hi = min(N, lo + chunk);
    const int tid = threadIdx.x;
    if (lo >= hi) {
        // emit empty sentinels
        if (tid < TOPK) {
            int o = (b * TSPLIT + s) * TOPK + tid;
            g_pv[o] = NEG_HUGE; g_pi[o] = 0x7fffffff;
        }
        return;
    }
    const float* __restrict__ row = g_sims + (size_t)b * N;

    float tv[TOPK]; int tix[TOPK];
#pragma unroll
    for (int e = 0; e < TOPK; e++) { tv[e] = NEG_HUGE; tix[e] = 0x7fffffff; }
    float mv = NEG_HUGE; int mi = 0x7fffffff; int mpos = 0;

    // vectorized: thread strides in float4s over [lo, hi)
    const int hi4 = lo + ((hi - lo) & ~3);               // full-float4 end
    for (int i = lo + tid * 4; i < hi4; i += 256 * 4) {
        float4 v4 = *(const float4*)&row[i];
        float vv[4] = {v4.x, v4.y, v4.z, v4.w};
#pragma unroll
        for (int p = 0; p < 4; p++) {
            int idx = i + p;
            float v = vv[p];
            if (better(v, idx, mv, mi)) {
                if (idx == 0) continue;                  // sims[:,0] = -inf
#pragma unroll
                for (int e = 0; e < TOPK; e++)
                    if (e == mpos) { tv[e] = v; tix[e] = idx; }
                mv = tv[0]; mi = tix[0]; mpos = 0;
#pragma unroll
                for (int e = 1; e < TOPK; e++)
                    if (better(mv, mi, tv[e], tix[e])) { mv = tv[e]; mi = tix[e]; mpos = e; }
            }
        }
    }
    // tail (non-multiple-of-4 remainder at very end of N)
    for (int i = hi4 + tid; i < hi; i += 256) {
        if (i == 0) continue;
        float v = row[i];
        if (better(v, i, mv, mi)) {
#pragma unroll
            for (int e = 0; e < TOPK; e++)
                if (e == mpos) { tv[e] = v; tix[e] = i; }
            mv = tv[0]; mi = tix[0]; mpos = 0;
#pragma unroll
            for (int e = 1; e < TOPK; e++)
                if (better(mv, mi, tv[e], tix[e])) { mv = tv[e]; mi = tix[e]; mpos = e; }
        }
    }

    __shared__ float bv[256 * TOPK];
    __shared__ int   bi[256 * TOPK];
    __shared__ float rv[256];
    __shared__ int   ri[256];
    __shared__ int   rp[256];
#pragma unroll
    for (int e = 0; e < TOPK; e++) { bv[tid * TOPK + e] = tv[e]; bi[tid * TOPK + e] = tix[e]; }
    __syncthreads();

    for (int sel = 0; sel < TOPK; sel++) {
        float lv = NEG_HUGE; int li = 0x7fffffff; int lp = 0;
        for (int p = tid; p < 256 * TOPK; p += 256) {
            float v = bv[p]; int ix = bi[p];
            if (better(v, ix, lv, li)) { lv = v; li = ix; lp = p; }
        }
        rv[tid] = lv; ri[tid] = li; rp[tid] = lp;
        __syncthreads();
        for (int st = 128; st > 0; st >>= 1) {
            if (tid < st) {
                if (better(rv[tid + st], ri[tid + st], rv[tid], ri[tid])) {
                    rv[tid] = rv[tid + st]; ri[tid] = ri[tid + st]; rp[tid] = rp[tid + st];
                }
            }
            __syncthreads();
        }
        if (tid == 0) {
            int o = (b * TSPLIT + s) * TOPK + sel;
            g_pv[o] = rv[0]; g_pi[o] = ri[0];
            bv[rp[0]] = NEG_HUGE; bi[rp[0]] = 0x7fffffff;
        }
        __syncthreads();
    }
}

// ------------------------- K3b: merge per-split partials --------------------
// 64 blocks (row each), 32 threads: select top-20 of TSPLIT*TOPK=160 entries
__global__ void topk_merge() {
    const int b = blockIdx.x;
    const int t = threadIdx.x;
    const int M = TSPLIT * TOPK;   // 160
    __shared__ float sv[TSPLIT * TOPK];
    __shared__ int   si[TSPLIT * TOPK];
    for (int p = t; p < M; p += 32) {
        sv[p] = g_pv[b * M + p];
        si[p] = g_pi[b * M + p];
    }
    __syncwarp();
    for (int sel = 0; sel < TOPK; sel++) {
        float lv = NEG_HUGE; int li = 0x7fffffff; int lp = -1;
        for (int p = t; p < M; p += 32) {
            if (better(sv[p], si[p], lv, li)) { lv = sv[p]; li = si[p]; lp = p; }
        }
#pragma unroll
        for (int o = 16; o; o >>= 1) {
            float ov = __shfl_xor_sync(0xffffffffu, lv, o);
            int   oi = __shfl_xor_sync(0xffffffffu, li, o);
            int   op = __shfl_xor_sync(0xffffffffu, lp, o);
            if (better(ov, oi, lv, li)) { lv = ov; li = oi; lp = op; }
        }
        if (t == 0) {
            g_topidx[b * TOPK + sel] = li;
            sv[lp] = NEG_HUGE; si[lp] = 0x7fffffff;
        }
        __syncwarp();
    }
}

// ------------------------- dtype detection (always runs) --------------------
__global__ void detect64(const int* __restrict__ p, int size_hint) {
    // size_hint = element count harness reported for target_item_id.
    // >= 2*B_SZ int32 words unambiguously means int64. Otherwise inspect
    // data: int64 targets in [1, N) have zero high words, int32 targets at
    // odd positions are nonzero (targets >= 1).
    if (size_hint >= 2 * B_SZ) { g_is64_flag = 1; return; }
    g_is64_flag = (p[1] == 0 && p[3] == 0 && p[5] == 0 && p[7] == 0) ? 1 : 0;
}

// ------------------------- K4: per-row fixed_idx + losses -------------------
__global__ void final_row(const float* __restrict__ emb,
                          const float* __restrict__ lin,
                          const int* __restrict__ tgt_raw,
                          float* __restrict__ out, int out_size) {
    __shared__ int   sidx[TOPK];
    __shared__ float slog[TOPK];
    __shared__ float sdot[TOPK];
    __shared__ int   s_replace;   // 1 if target NOT contained (replace slot 19)
    const int b = blockIdx.x, t = threadIdx.x;
    const int is64 = g_is64_flag;
    const int tgt = is64 ? tgt_raw[2 * b] : tgt_raw[b];

    if (t < TOPK) sidx[t] = g_topidx[b * TOPK + t];
    __syncthreads();

    if (t < TOPK) {
        const float* e = &emb[(size_t)sidx[t] * DIM];
        const float* te = &emb[(size_t)tgt * DIM];
        float l = 0.f, d = 0.f;
#pragma unroll 8
        for (int k = 0; k < DIM; k++) {
            float ev = e[k];
            l += ev * lin[k];
            d += ev * te[k];
        }
        slog[t] = l;
        sdot[t] = d;
    }
    __syncthreads();

    if (t == 0) {
        int j = -1;
        for (int k = 0; k < TOPK; k++) if (sidx[k] == tgt) { j = k; break; }
        bool contains = (j >= 0);
        if (!contains) j = TOPK - 1;
        // CE uses logits of the ORIGINAL top-20 embeddings (top_k_emb in ref),
        // with target position taken from fixed_idx — i.e. slot j's original
        // logit even when slot 19's index was replaced by the target.
        float m = NEG_HUGE;
        for (int k = 0; k < TOPK; k++) m = fmaxf(m, slog[k]);
        float se = 0.f;
        for (int k = 0; k < TOPK; k++) se += expf(slog[k] - m);
        float ce = -(slog[j] - m - logf(se));
        float cl = 0.f;
        for (int k = 0; k < TOPK; k++)
            if (k != j) cl += 1.f - 1.f / (1.f + expf(-sdot[k]));
        cl *= (1.f / (TOPK - 1));
        g_rowloss[b] = ce + cl;
        s_replace = contains ? 0 : 1;
    }
    __syncthreads();

    if (t < TOPK) {
        int v = sidx[t];
        if (t == TOPK - 1 && s_replace) v = tgt;
        int o = b * TOPK + t;
        if (o < out_size) out[o] = (float)v;
    }
}

// ------------------------- K5: loss reduction -------------------------------
__global__ void loss_kernel(float* __restrict__ out, int out_size) {
    __shared__ float s[B_SZ];
    int t = threadIdx.x;
    s[t] = g_rowloss[t];
    __syncthreads();
    for (int k = 32; k > 0; k >>= 1) {
        if (t < k) s[t] += s[t + k];
        __syncthreads();
    }
    if (t == 0 && out_size > B_SZ * TOPK) out[B_SZ * TOPK] = s[0] * (1.0f / B_SZ);
}

// ------------------------- launch -------------------------------------------
extern "C" void kernel_launch(void* const* d_in, const int* in_sizes, int n_in,
                              void* d_out, int out_size) {
    const float* q   = (const float*)d_in[0];
    const float* W1  = (const float*)d_in[1];
    const float* b1  = (const float*)d_in[2];
    const float* W2  = (const float*)d_in[3];
    const float* b2  = (const float*)d_in[4];
    const float* emb = (const float*)d_in[5];
    const float* lin = (const float*)d_in[6];
    const int*   tgt = (const int*)d_in[7];
    int N = in_sizes[5] / DIM;
    if (N > MAXN) N = MAXN;
    float* out = (float*)d_out;

    detect64<<<1, 1>>>(tgt, in_sizes[7]);
    gemm1_partial<<<dim3(8, 16), 256>>>(q, W1);
    gemm1_reduce<<<(B_SZ * LD) / 256, 256>>>(b1);
    gemm2_norm<<<B_SZ, DIM>>>(W2, b2);
    sims_kernel<<<(N + 127) / 128, 256>>>(emb, N);
    topk_part<<<dim3(B_SZ, TSPLIT), 256>>>(N);
    topk_merge<<<B_SZ, 32>>>();
    final_row<<<B_SZ, 64>>>(emb, lin, tgt, out, out_size);
    loss_kernel<<<1, B_SZ>>>(out, out_size);
}

// round 9
// speedup vs baseline: 1.1406x; 1.1406x over previous
#include <cuda_runtime.h>
#include <cuda_bf16.h>
#include <math.h>

// ---------------------------------------------------------------------------
// CandiRec: query MLP -> cosine sims vs 500k items -> top-20 -> fixed_idx + loss
// Shapes: B=64, LQ=4096, LD=512, D=128, N=500000 (N read at runtime)
// ---------------------------------------------------------------------------

#define B_SZ   64
#define LQ     4096
#define LD     512
#define DIM    128
#define MAXN   500000
#define TOPK   20
#define TSPLIT 8
#define KCH    16
#define ITEMS  256
#define NEG_HUGE (-3.402823466e38f)

// ------------------------- device scratch (no allocs allowed) ---------------
__device__ float g_hpart[16 * B_SZ * LD];        // split-K partials of q@W1
__device__ float g_h[B_SZ * LD];                 // h = q@W1 + b1
__device__ float g_qn[B_SZ * DIM];               // l2-normalized query
__device__ float g_sims[(size_t)B_SZ * MAXN];    // 128 MB sims scratch
__device__ float g_pv[B_SZ * TSPLIT * TOPK];     // per-split partial topk vals
__device__ int   g_pi[B_SZ * TSPLIT * TOPK];     // per-split partial topk idx
__device__ int   g_topidx[B_SZ * TOPK];
__device__ float g_rowloss[B_SZ];
__device__ int   g_is64_flag;                    // target dtype: 1 = int64

// ------------------------- helpers -----------------------------------------
__device__ __forceinline__ unsigned long long pack2(float x, float y) {
    unsigned long long r;
    asm("mov.b64 %0, {%1, %2};" : "=l"(r) : "f"(x), "f"(y));
    return r;
}
__device__ __forceinline__ float2 unpack2(unsigned long long v) {
    float2 r;
    asm("mov.b64 {%0, %1}, %2;" : "=f"(r.x), "=f"(r.y) : "l"(v));
    return r;
}
#define FMA2(acc, a, b) \
    asm("fma.rn.f32x2 %0, %1, %2, %3;" : "=l"(acc) : "l"(a), "l"(b), "l"(acc))

__device__ __forceinline__ bool better(float v, int i, float v2, int i2) {
    return (v > v2) || (v == v2 && i < i2);
}

// ------------------------- K1a: h partials = q @ W1 (split-K) ---------------
// grid (8 col-chunks of 64, 16 k-splits of 256), 256 threads
__global__ void __launch_bounds__(256) gemm1_partial(const float* __restrict__ q,
                                                     const float* __restrict__ W1) {
    __shared__ float shq[32][68];
    __shared__ float shw[32][68];
    const int cb = blockIdx.x * 64;
    const int k0 = blockIdx.y * 256;
    const int tid = threadIdx.x;
    const int r0 = (tid >> 4) * 4;
    const int c0 = (tid & 15) * 4;
    unsigned long long acc2[4][2];
#pragma unroll
    for (int r = 0; r < 4; r++) { acc2[r][0] = 0ull; acc2[r][1] = 0ull; }

    for (int kc = 0; kc < 256; kc += 32) {
#pragma unroll
        for (int u = 0; u < 2; u++) {
            int f = u * 256 + tid;
            int row = f >> 3;
            int jj = (f & 7) * 4;
            float4 v = *(const float4*)&q[(size_t)row * LQ + k0 + kc + jj];
            shq[jj + 0][row] = v.x; shq[jj + 1][row] = v.y;
            shq[jj + 2][row] = v.z; shq[jj + 3][row] = v.w;
        }
#pragma unroll
        for (int u = 0; u < 2; u++) {
            int f = u * 256 + tid;
            int kk = f >> 4;
            int cc = (f & 15) * 4;
            float4 v = *(const float4*)&W1[(size_t)(k0 + kc + kk) * LD + cb + cc];
            *(float4*)&shw[kk][cc] = v;
        }
        __syncthreads();
#pragma unroll 8
        for (int k = 0; k < 32; k++) {
            float4 qv = *(const float4*)&shq[k][r0];
            float4 wv = *(const float4*)&shw[k][c0];
            unsigned long long w01 = pack2(wv.x, wv.y);
            unsigned long long w23 = pack2(wv.z, wv.w);
            float qarr[4] = {qv.x, qv.y, qv.z, qv.w};
#pragma unroll
            for (int r = 0; r < 4; r++) {
                unsigned long long qq = pack2(qarr[r], qarr[r]);
                FMA2(acc2[r][0], w01, qq);
                FMA2(acc2[r][1], w23, qq);
            }
        }
        __syncthreads();
    }
#pragma unroll
    for (int r = 0; r < 4; r++) {
        float2 a01 = unpack2(acc2[r][0]);
        float2 a23 = unpack2(acc2[r][1]);
        float* dst = &g_hpart[((size_t)blockIdx.y * B_SZ + r0 + r) * LD + cb + c0];
        dst[0] = a01.x; dst[1] = a01.y; dst[2] = a23.x; dst[3] = a23.y;
    }
}

// ------------------------- K1a': reduce split-K + bias ----------------------
__global__ void gemm1_reduce(const float* __restrict__ b1) {
    int o = blockIdx.x * 256 + threadIdx.x;
    int c = o & (LD - 1);
    float s = b1[c];
#pragma unroll
    for (int y = 0; y < 16; y++) s += g_hpart[(size_t)y * (B_SZ * LD) + o];
    g_h[o] = s;
}

// ------------------------- K1b: query = h@W2 + b2, l2-normalize -------------
// 64 blocks, 512 threads: k split across 4 warpsets + 4-wide ILP
__global__ void __launch_bounds__(512) gemm2_norm(const float* __restrict__ W2,
                                                  const float* __restrict__ b2) {
    __shared__ float hrow[LD];
    __shared__ float part[4][DIM];
    __shared__ float sqsum[4];
    const int b = blockIdx.x, t = threadIdx.x;
    hrow[t] = g_h[(size_t)b * LD + t];
    __syncthreads();
    const int col = t & (DIM - 1);
    const int kq = t >> 7;            // 0..3
    const int kb = kq * 128;
    float a0 = 0.f, a1 = 0.f, a2 = 0.f, a3 = 0.f;
#pragma unroll 8
    for (int k = 0; k < 128; k += 4) {
        a0 += hrow[kb + k + 0] * W2[(size_t)(kb + k + 0) * DIM + col];
        a1 += hrow[kb + k + 1] * W2[(size_t)(kb + k + 1) * DIM + col];
        a2 += hrow[kb + k + 2] * W2[(size_t)(kb + k + 2) * DIM + col];
        a3 += hrow[kb + k + 3] * W2[(size_t)(kb + k + 3) * DIM + col];
    }
    part[kq][col] = (a0 + a1) + (a2 + a3);
    __syncthreads();
    float s = 0.f;
    if (t < DIM) s = part[0][t] + part[1][t] + part[2][t] + part[3][t] + b2[t];
    float sq = s * s;
#pragma unroll
    for (int o = 16; o; o >>= 1) sq += __shfl_xor_sync(0xffffffffu, sq, o);
    if (t < DIM && (t & 31) == 0) sqsum[t >> 5] = sq;
    __syncthreads();
    if (t < DIM) {
        float tot = sqsum[0] + sqsum[1] + sqsum[2] + sqsum[3];
        g_qn[(size_t)b * DIM + t] = s * rsqrtf(tot + 1e-12f);
    }
}

// ------------------------- K2: sims = qn @ l2n(emb).T ----------------------
// block: 256 threads, tile 64 rows x 256 items; thread tile 8 rows x 8 items.
// Conflict-free LDS (lane ig reads consecutive 16B at 4*ig), q prepacked as
// duplicated (q,q) u64 broadcast so the inner loop is pure LDS + FMA2.
__global__ void __launch_bounds__(256, 1) sims_kernel(const float* __restrict__ emb, int N) {
    __shared__ float sh_e[KCH][ITEMS + 4];                    // 16 x 260
    __shared__ unsigned long long sh_qq[KCH][B_SZ + 2];       // 16 x 66 (q,q) pairs
    __shared__ float sh_inv[ITEMS];
    const int i0 = blockIdx.x * ITEMS;
    const int tid = threadIdx.x;
    const int rg = tid >> 5;          // 0..7 row group (uniform per warp)
    const int ig = tid & 31;          // 0..31 item group
    const int r0 = rg * 8;
    const int c0 = ig * 4;

    unsigned long long acc[8][4];     // [row][item-pair]
#pragma unroll
    for (int j = 0; j < 8; j++)
#pragma unroll
        for (int p = 0; p < 4; p++) acc[j][p] = 0ull;

    float ss = 0.f;                   // sum of squares for item tid

    for (int kc = 0; kc < DIM; kc += KCH) {
        // load emb chunk: 256 items x 16 k -> sh_e[k][item]
#pragma unroll
        for (int u = 0; u < 4; u++) {
            int f = u * 256 + tid;                 // 0..1023
            int item = f >> 2;                     // 0..255
            int j4 = (f & 3) * 4;                  // k offset within chunk
            int gi = i0 + item;
            float4 v = make_float4(0.f, 0.f, 0.f, 0.f);
            if (gi < N) v = *(const float4*)&emb[(size_t)gi * DIM + kc + j4];
            sh_e[j4 + 0][item] = v.x; sh_e[j4 + 1][item] = v.y;
            sh_e[j4 + 2][item] = v.z; sh_e[j4 + 3][item] = v.w;
        }
        // load qn chunk: 64 rows x 16 k -> sh_qq[k][row] duplicated pairs
        {
            int row = tid >> 2;                    // 0..63
            int j4 = (tid & 3) * 4;
            float4 v = *(const float4*)&g_qn[(size_t)row * DIM + kc + j4];
            sh_qq[j4 + 0][row] = pack2(v.x, v.x);
            sh_qq[j4 + 1][row] = pack2(v.y, v.y);
            sh_qq[j4 + 2][row] = pack2(v.z, v.z);
            sh_qq[j4 + 3][row] = pack2(v.w, v.w);
        }
        __syncthreads();

        // per-item sum of squares (thread owns item tid; conflict-free scalar)
#pragma unroll
        for (int k = 0; k < KCH; k++) { float e = sh_e[k][tid]; ss += e * e; }

#pragma unroll
        for (int k = 0; k < KCH; k++) {
            float4 e0 = *(const float4*)&sh_e[k][c0];
            float4 e1 = *(const float4*)&sh_e[k][128 + c0];
            unsigned long long ea = pack2(e0.x, e0.y);
            unsigned long long eb = pack2(e0.z, e0.w);
            unsigned long long ec = pack2(e1.x, e1.y);
            unsigned long long ed = pack2(e1.z, e1.w);
#pragma unroll
            for (int j = 0; j < 8; j++) {
                unsigned long long qq = sh_qq[k][r0 + j];   // warp-uniform broadcast
                FMA2(acc[j][0], ea, qq);
                FMA2(acc[j][1], eb, qq);
                FMA2(acc[j][2], ec, qq);
                FMA2(acc[j][3], ed, qq);
            }
        }
        __syncthreads();
    }

    sh_inv[tid] = rsqrtf(ss + 1e-12f);
    __syncthreads();

    const float i00 = sh_inv[c0 + 0], i01 = sh_inv[c0 + 1];
    const float i02 = sh_inv[c0 + 2], i03 = sh_inv[c0 + 3];
    const float i10 = sh_inv[128 + c0 + 0], i11 = sh_inv[128 + c0 + 1];
    const float i12 = sh_inv[128 + c0 + 2], i13 = sh_inv[128 + c0 + 3];
    // STG.128 requires 16B-aligned addresses: row*N + i0 + c0 must be 0 mod 4
    // for every row -> need N % 4 == 0 in addition to full tile coverage.
    const bool full = (i0 + ITEMS <= N) && ((N & 3) == 0);
#pragma unroll
    for (int j = 0; j < 8; j++) {
        size_t base = (size_t)(r0 + j) * N + i0;
        float2 a0 = unpack2(acc[j][0]);
        float2 a1 = unpack2(acc[j][1]);
        float2 a2 = unpack2(acc[j][2]);
        float2 a3 = unpack2(acc[j][3]);
        float4 v0 = make_float4(a0.x * i00, a0.y * i01, a1.x * i02, a1.y * i03);
        float4 v1 = make_float4(a2.x * i10, a2.y * i11, a3.x * i12, a3.y * i13);
        if (full) {
            *(float4*)&g_sims[base + c0] = v0;
            *(float4*)&g_sims[base + 128 + c0] = v1;
        } else {
            float lo[4] = {v0.x, v0.y, v0.z, v0.w};
            float hi[4] = {v1.x, v1.y, v1.z, v1.w};
#pragma unroll
            for (int p = 0; p < 4; p++) {
                if (i0 + c0 + p < N)       g_sims[base + c0 + p] = lo[p];
                if (i0 + 128 + c0 + p < N) g_sims[base + 128 + c0 + p] = hi[p];
            }
        }
    }
}

// ------------------------- K3a: per-(row,split) partial top-20 --------------
__global__ void __launch_bounds__(256) topk_part(int N) {
    const int b = blockIdx.x;
    const int s = blockIdx.y;
    int chunk = ((N + TSPLIT - 1) / TSPLIT + 3) & ~3;
    const int lo = s * chunk;
    const int hi = min(N, lo + chunk);
    const int tid = threadIdx.x;
    if (lo >= hi) {
        if (tid < TOPK) {
            int o = (b * TSPLIT + s) * TOPK + tid;
            g_pv[o] = NEG_HUGE; g_pi[o] = 0x7fffffff;
        }
        return;
    }
    const float* __restrict__ row = g_sims + (size_t)b * N;

    float tv[TOPK]; int tix[TOPK];
#pragma unroll
    for (int e = 0; e < TOPK; e++) { tv[e] = NEG_HUGE; tix[e] = 0x7fffffff; }
    float mv = NEG_HUGE; int mi = 0x7fffffff; int mpos = 0;

    // LDG.128 path requires row base 16B-aligned for all b -> N % 4 == 0.
    const int hi4 = ((N & 3) == 0) ? (lo + ((hi - lo) & ~3)) : lo;
    for (int i = lo + tid * 4; i < hi4; i += 256 * 4) {
        float4 v4 = *(const float4*)&row[i];
        float vv[4] = {v4.x, v4.y, v4.z, v4.w};
#pragma unroll
        for (int p = 0; p < 4; p++) {
            int idx = i + p;
            float v = vv[p];
            if (better(v, idx, mv, mi)) {
                if (idx == 0) continue;
#pragma unroll
                for (int e = 0; e < TOPK; e++)
                    if (e == mpos) { tv[e] = v; tix[e] = idx; }
                mv = tv[0]; mi = tix[0]; mpos = 0;
#pragma unroll
                for (int e = 1; e < TOPK; e++)
                    if (better(mv, mi, tv[e], tix[e])) { mv = tv[e]; mi = tix[e]; mpos = e; }
            }
        }
    }
    for (int i = hi4 + tid; i < hi; i += 256) {
        if (i == 0) continue;
        float v = row[i];
        if (better(v, i, mv, mi)) {
#pragma unroll
            for (int e = 0; e < TOPK; e++)
                if (e == mpos) { tv[e] = v; tix[e] = i; }
            mv = tv[0]; mi = tix[0]; mpos = 0;
#pragma unroll
            for (int e = 1; e < TOPK; e++)
                if (better(mv, mi, tv[e], tix[e])) { mv = tv[e]; mi = tix[e]; mpos = e; }
        }
    }

    __shared__ float bv[256 * TOPK];
    __shared__ int   bi[256 * TOPK];
    __shared__ float rv[256];
    __shared__ int   ri[256];
    __shared__ int   rp[256];
#pragma unroll
    for (int e = 0; e < TOPK; e++) { bv[tid * TOPK + e] = tv[e]; bi[tid * TOPK + e] = tix[e]; }
    __syncthreads();

    for (int sel = 0; sel < TOPK; sel++) {
        float lv = NEG_HUGE; int li = 0x7fffffff; int lp = 0;
        for (int p = tid; p < 256 * TOPK; p += 256) {
            float v = bv[p]; int ix = bi[p];
            if (better(v, ix, lv, li)) { lv = v; li = ix; lp = p; }
        }
        rv[tid] = lv; ri[tid] = li; rp[tid] = lp;
        __syncthreads();
        for (int st = 128; st > 0; st >>= 1) {
            if (tid < st) {
                if (better(rv[tid + st], ri[tid + st], rv[tid], ri[tid])) {
                    rv[tid] = rv[tid + st]; ri[tid] = ri[tid + st]; rp[tid] = rp[tid + st];
                }
            }
            __syncthreads();
        }
        if (tid == 0) {
            int o = (b * TSPLIT + s) * TOPK + sel;
            g_pv[o] = rv[0]; g_pi[o] = ri[0];
            bv[rp[0]] = NEG_HUGE; bi[rp[0]] = 0x7fffffff;
        }
        __syncthreads();
    }
}

// ------------------------- K3b: merge per-split partials --------------------
__global__ void topk_merge() {
    const int b = blockIdx.x;
    const int t = threadIdx.x;
    const int M = TSPLIT * TOPK;
    __shared__ float sv[TSPLIT * TOPK];
    __shared__ int   si[TSPLIT * TOPK];
    for (int p = t; p < M; p += 32) {
        sv[p] = g_pv[b * M + p];
        si[p] = g_pi[b * M + p];
    }
    __syncwarp();
    for (int sel = 0; sel < TOPK; sel++) {
        float lv = NEG_HUGE; int li = 0x7fffffff; int lp = -1;
        for (int p = t; p < M; p += 32) {
            if (better(sv[p], si[p], lv, li)) { lv = sv[p]; li = si[p]; lp = p; }
        }
#pragma unroll
        for (int o = 16; o; o >>= 1) {
            float ov = __shfl_xor_sync(0xffffffffu, lv, o);
            int   oi = __shfl_xor_sync(0xffffffffu, li, o);
            int   op = __shfl_xor_sync(0xffffffffu, lp, o);
            if (better(ov, oi, lv, li)) { lv = ov; li = oi; lp = op; }
        }
        if (t == 0) {
            g_topidx[b * TOPK + sel] = li;
            sv[lp] = NEG_HUGE; si[lp] = 0x7fffffff;
        }
        __syncwarp();
    }
}

// ------------------------- dtype detection (always runs) --------------------
__global__ void detect64(const int* __restrict__ p, int size_hint) {
    if (size_hint >= 2 * B_SZ) { g_is64_flag = 1; return; }
    g_is64_flag = (p[1] == 0 && p[3] == 0 && p[5] == 0 && p[7] == 0) ? 1 : 0;
}

// ------------------------- K4: per-row fixed_idx + losses -------------------
__global__ void final_row(const float* __restrict__ emb,
                          const float* __restrict__ lin,
                          const int* __restrict__ tgt_raw,
                          float* __restrict__ out, int out_size) {
    __shared__ int   sidx[TOPK];
    __shared__ float slog[TOPK];
    __shared__ float sdot[TOPK];
    __shared__ int   s_replace;
    const int b = blockIdx.x, t = threadIdx.x;
    const int is64 = g_is64_flag;
    const int tgt = is64 ? tgt_raw[2 * b] : tgt_raw[b];

    if (t < TOPK) sidx[t] = g_topidx[b * TOPK + t];
    __syncthreads();

    if (t < TOPK) {
        const float* e = &emb[(size_t)sidx[t] * DIM];
        const float* te = &emb[(size_t)tgt * DIM];
        float l = 0.f, d = 0.f;
#pragma unroll 8
        for (int k = 0; k < DIM; k++) {
            float ev = e[k];
            l += ev * lin[k];
            d += ev * te[k];
        }
        slog[t] = l;
        sdot[t] = d;
    }
    __syncthreads();

    if (t == 0) {
        int j = -1;
        for (int k = 0; k < TOPK; k++) if (sidx[k] == tgt) { j = k; break; }
        bool contains = (j >= 0);
        if (!contains) j = TOPK - 1;
        float m = NEG_HUGE;
        for (int k = 0; k < TOPK; k++) m = fmaxf(m, slog[k]);
        float se = 0.f;
        for (int k = 0; k < TOPK; k++) se += expf(slog[k] - m);
        float ce = -(slog[j] - m - logf(se));
        float cl = 0.f;
        for (int k = 0; k < TOPK; k++)
            if (k != j) cl += 1.f - 1.f / (1.f + expf(-sdot[k]));
        cl *= (1.f / (TOPK - 1));
        g_rowloss[b] = ce + cl;
        s_replace = contains ? 0 : 1;
    }
    __syncthreads();

    if (t < TOPK) {
        int v = sidx[t];
        if (t == TOPK - 1 && s_replace) v = tgt;
        int o = b * TOPK + t;
        if (o < out_size) out[o] = (float)v;
    }
}

// ------------------------- K5: loss reduction -------------------------------
__global__ void loss_kernel(float* __restrict__ out, int out_size) {
    __shared__ float s[B_SZ];
    int t = threadIdx.x;
    s[t] = g_rowloss[t];
    __syncthreads();
    for (int k = 32; k > 0; k >>= 1) {
        if (t < k) s[t] += s[t + k];
        __syncthreads();
    }
    if (t == 0 && out_size > B_SZ * TOPK) out[B_SZ * TOPK] = s[0] * (1.0f / B_SZ);
}

// ------------------------- launch -------------------------------------------
extern "C" void kernel_launch(void* const* d_in, const int* in_sizes, int n_in,
                              void* d_out, int out_size) {
    const float* q   = (const float*)d_in[0];
    const float* W1  = (const float*)d_in[1];
    const float* b1  = (const float*)d_in[2];
    const float* W2  = (const float*)d_in[3];
    const float* b2  = (const float*)d_in[4];
    const float* emb = (const float*)d_in[5];
    const float* lin = (const float*)d_in[6];
    const int*   tgt = (const int*)d_in[7];
    int N = in_sizes[5] / DIM;
    if (N > MAXN) N = MAXN;
    float* out = (float*)d_out;

    detect64<<<1, 1>>>(tgt, in_sizes[7]);
    gemm1_partial<<<dim3(8, 16), 256>>>(q, W1);
    gemm1_reduce<<<(B_SZ * LD) / 256, 256>>>(b1);
    gemm2_norm<<<B_SZ, 512>>>(W2, b2);
    sims_kernel<<<(N + ITEMS - 1) / ITEMS, 256>>>(emb, N);
    topk_part<<<dim3(B_SZ, TSPLIT), 256>>>(N);
    topk_merge<<<B_SZ, 32>>>();
    final_row<<<B_SZ, 64>>>(emb, lin, tgt, out, out_size);
    loss_kernel<<<1, B_SZ>>>(out, out_size);
}